// round 15
// baseline (speedup 1.0000x reference)
#include <cuda_runtime.h>
#include <cuda_bf16.h>
#include <math.h>
#include <stdint.h>

// ---------------------------------------------------------------------------
// Problem constants
// ---------------------------------------------------------------------------
#define NROW  16384
#define DMODEL 512
#define DFF   2048
#define LLEN  256
#define HN    8
#define NSEG  (NROW*8)
#define SC2   (1.0f/64.0f)

// ---------------------------------------------------------------------------
// Scratch (fp32)
// ---------------------------------------------------------------------------
__device__ float g_xen [NROW*DMODEL];
__device__ float g_xde [NROW*DMODEL];
__device__ float g_v   [NROW*DMODEL];
__device__ float g_bufA[NROW*DMODEL];
__device__ float g_bufB[NROW*DMODEL];
__device__ float g_enc [NROW*DMODEL];
__device__ float g_ffo [NROW*DMODEL];
__device__ float g_qs  [NSEG];
__device__ float g_ks  [NSEG];
__device__ float g_a2  [LLEN*HN*64];
__device__ float g_s1  [LLEN*HN];
__device__ float g_wg  [6*8*512];

// Split bf16 buffers (hi/lo)
__device__ __nv_bfloat16 g_sxen_h[4194304], g_sxen_l[4194304];
__device__ __nv_bfloat16 g_sxde_h[4194304], g_sxde_l[4194304];
__device__ __nv_bfloat16 g_xen_h [NROW*DMODEL], g_xen_l [NROW*DMODEL];
__device__ __nv_bfloat16 g_xde_h [NROW*DMODEL], g_xde_l [NROW*DMODEL];
__device__ __nv_bfloat16 g_enc_h [NROW*DMODEL], g_enc_l [NROW*DMODEL];
__device__ __nv_bfloat16 g_bufA_h[NROW*DMODEL], g_bufA_l[NROW*DMODEL];
__device__ __nv_bfloat16 g_bufB_h[NROW*DMODEL], g_bufB_l[NROW*DMODEL];
__device__ __nv_bfloat16 g_ffh_h [NROW*DFF],    g_ffh_l [NROW*DFF];
__device__ __nv_bfloat16 g_win_h [32768],       g_win_l [32768];
#define NWSPLIT 4980736
__device__ __nv_bfloat16 g_wsp_h[NWSPLIT], g_wsp_l[NWSPLIT];
#define WV0 0
#define WV1 262144
#define WV2 524288
#define W1E 786432
#define W2E 1835008
#define W1D 2883584
#define W2D 3932160

// ---------------------------------------------------------------------------
// Helpers
// ---------------------------------------------------------------------------
__device__ __forceinline__ uint32_t smem_u32(const void* p) {
    return (uint32_t)__cvta_generic_to_shared(p);
}
__device__ __forceinline__ void ldsm_x4(uint32_t* r, uint32_t addr) {
    asm volatile("ldmatrix.sync.aligned.m8n8.x4.shared.b16 {%0,%1,%2,%3}, [%4];"
        : "=r"(r[0]), "=r"(r[1]), "=r"(r[2]), "=r"(r[3]) : "r"(addr));
}
__device__ __forceinline__ void ldsm_x4t(uint32_t* r, uint32_t addr) {
    asm volatile("ldmatrix.sync.aligned.m8n8.x4.trans.shared.b16 {%0,%1,%2,%3}, [%4];"
        : "=r"(r[0]), "=r"(r[1]), "=r"(r[2]), "=r"(r[3]) : "r"(addr));
}
__device__ __forceinline__ void mma_bf16(float* c, const uint32_t* a, const uint32_t* b) {
    asm volatile(
        "mma.sync.aligned.m16n8k16.row.col.f32.bf16.bf16.f32 "
        "{%0,%1,%2,%3},{%4,%5,%6,%7},{%8,%9},{%0,%1,%2,%3};"
        : "+f"(c[0]), "+f"(c[1]), "+f"(c[2]), "+f"(c[3])
        : "r"(a[0]), "r"(a[1]), "r"(a[2]), "r"(a[3]), "r"(b[0]), "r"(b[1]));
}
__device__ __forceinline__ void cp16(uint32_t dst, const void* src) {
    asm volatile("cp.async.cg.shared.global [%0], [%1], 16;" :: "r"(dst), "l"(src));
}
__device__ __forceinline__ void cp_commit() {
    asm volatile("cp.async.commit_group;");
}
template<int N> __device__ __forceinline__ void cp_wait() {
    asm volatile("cp.async.wait_group %0;" :: "n"(N));
}
__device__ __forceinline__ void bsplit(float x, unsigned short& h, unsigned short& l) {
    __nv_bfloat16 hb = __float2bfloat16(x);
    float r = x - __bfloat162float(hb);
    h = __bfloat16_as_ushort(hb);
    l = __bfloat16_as_ushort(__float2bfloat16(r));
}
__device__ __forceinline__ void bsplit2(float a, float b, uint32_t& hh, uint32_t& ll) {
    unsigned short h0,l0,h1,l1;
    bsplit(a,h0,l0); bsplit(b,h1,l1);
    hh = (uint32_t)h0 | ((uint32_t)h1 << 16);
    ll = (uint32_t)l0 | ((uint32_t)l1 << 16);
}

// ---------------------------------------------------------------------------
// k_split: fp32 -> (hi,lo) bf16.  16 floats/thread.
// ---------------------------------------------------------------------------
__global__ void __launch_bounds__(256) k_split(const float* __restrict__ x,
                                               __nv_bfloat16* __restrict__ hi,
                                               __nv_bfloat16* __restrict__ lo,
                                               int n)
{
    int i = (blockIdx.x*256 + threadIdx.x)*16;
    if (i >= n) return;
    float4 v0 = *(const float4*)(x + i);
    float4 v1 = *(const float4*)(x + i + 4);
    float4 v2 = *(const float4*)(x + i + 8);
    float4 v3 = *(const float4*)(x + i + 12);
    uint4 H, L;
    bsplit2(v0.x, v0.y, H.x, L.x);
    bsplit2(v0.z, v0.w, H.y, L.y);
    bsplit2(v1.x, v1.y, H.z, L.z);
    bsplit2(v1.z, v1.w, H.w, L.w);
    *(uint4*)&hi[i] = H;
    *(uint4*)&lo[i] = L;
    bsplit2(v2.x, v2.y, H.x, L.x);
    bsplit2(v2.z, v2.w, H.y, L.y);
    bsplit2(v3.x, v3.y, H.z, L.z);
    bsplit2(v3.z, v3.w, H.w, L.w);
    *(uint4*)&hi[i + 8] = H;
    *(uint4*)&lo[i + 8] = L;
}

// ---------------------------------------------------------------------------
// Pipelined split-bf16 tensor GEMM (3 passes).
// Tile 128x64x32, 256 threads, 8 warps (4m x 2n), 2 CTA/SM.
// flags: b0 bias, b1 relu, b2 write split (Ch,Cl), b3 skip fp32 C.
// ---------------------------------------------------------------------------
#define STAGE_BYTES 28672
#define OFF_AL 10240
#define OFF_BH 20480
#define OFF_BL 24576
#define GEMM_SMEM (3*STAGE_BYTES)

extern __shared__ char dsm[];

__device__ __forceinline__ void ld_stage(uint32_t sb,
    const __nv_bfloat16* __restrict__ Ah, const __nv_bfloat16* __restrict__ Al,
    const __nv_bfloat16* __restrict__ Bh, const __nv_bfloat16* __restrict__ Bl,
    int K, int N, int bm, int bn, int tid, int k0)
{
    int rowA = tid >> 2, kc = tid & 3;
    size_t aoff0 = (size_t)(bm + rowA)*K + k0 + kc*8;
    size_t aoff1 = aoff0 + (size_t)64*K;
    uint32_t dA = sb + rowA*80 + kc*16;
    cp16(dA,            Ah + aoff0);
    cp16(dA + 64*80,    Ah + aoff1);
    cp16(dA + OFF_AL,         Al + aoff0);
    cp16(dA + OFF_AL + 64*80, Al + aoff1);

    int kr = tid >> 3, nc = tid & 7;
    size_t boff = (size_t)(k0 + kr)*N + bn + nc*8;
    uint32_t dB = sb + OFF_BH + kr*128 + ((nc ^ (kr & 7)) << 4);
    cp16(dB,        Bh + boff);
    cp16(dB + 4096, Bl + boff);
}

__global__ void __launch_bounds__(256, 2) k_bgemm(
    const __nv_bfloat16* __restrict__ Ah, const __nv_bfloat16* __restrict__ Al,
    const __nv_bfloat16* __restrict__ Bh, const __nv_bfloat16* __restrict__ Bl,
    const float* __restrict__ bias, float* __restrict__ C,
    __nv_bfloat16* __restrict__ Ch, __nv_bfloat16* __restrict__ Cl,
    int M, int N, int K, int flags)
{
    const int tid = threadIdx.x;
    const int bm = blockIdx.y * 128;
    const int bn = blockIdx.x * 64;
    const int w = tid >> 5, lane = tid & 31;
    const int wm = (w >> 1) * 32;
    const int wn = (w & 1) * 32;
    const int g = lane >> 2, tg = lane & 3;
    const uint32_t sbase = smem_u32(dsm);

    float acc[2][4][4];
#pragma unroll
    for (int mf = 0; mf < 2; mf++)
#pragma unroll
        for (int nf = 0; nf < 4; nf++)
#pragma unroll
            for (int i = 0; i < 4; i++) acc[mf][nf][i] = 0.f;

    const int a_off0 = (wm + (lane & 15))*40 + (lane >> 4)*8;
    const int bkl  = (lane & 7) + ((lane >> 3) & 1)*8;
    const int bncl = lane >> 4;

    const int T = K / 32;

    ld_stage(sbase,               Ah, Al, Bh, Bl, K, N, bm, bn, tid, 0);
    cp_commit();
    ld_stage(sbase + STAGE_BYTES, Ah, Al, Bh, Bl, K, N, bm, bn, tid, 32);
    cp_commit();

    for (int kt = 0; kt < T; ++kt) {
        cp_wait<1>();
        __syncthreads();

        if (kt + 2 < T) {
            int buf = (kt + 2) % 3;
            ld_stage(sbase + buf*STAGE_BYTES, Ah, Al, Bh, Bl, K, N, bm, bn,
                     tid, (kt + 2)*32);
        }
        cp_commit();

        const uint32_t bA = sbase + (kt % 3)*STAGE_BYTES;
        const uint32_t bB = bA + OFF_BH;
#pragma unroll
        for (int ks2 = 0; ks2 < 32; ks2 += 16) {
            uint32_t ah[2][4], al[2][4];
#pragma unroll
            for (int mf = 0; mf < 2; mf++) {
                int eoff = a_off0 + mf*640 + ks2;
                ldsm_x4(ah[mf], bA + 2*eoff);
                ldsm_x4(al[mf], bA + OFF_AL + 2*eoff);
            }
            uint32_t bh[4][2], bl[4][2];
#pragma unroll
            for (int nf2 = 0; nf2 < 2; nf2++) {
                int k = ks2 + bkl;
                int nc = (wn >> 3) + nf2*2 + bncl;
                int eoff = k*64 + ((nc ^ (k & 7)) << 3);
                uint32_t r[4];
                ldsm_x4t(r, bB + 2*eoff);
                bh[nf2*2][0] = r[0]; bh[nf2*2][1] = r[1];
                bh[nf2*2+1][0] = r[2]; bh[nf2*2+1][1] = r[3];
                ldsm_x4t(r, bB + 4096 + 2*eoff);
                bl[nf2*2][0] = r[0]; bl[nf2*2][1] = r[1];
                bl[nf2*2+1][0] = r[2]; bl[nf2*2+1][1] = r[3];
            }
#pragma unroll
            for (int mf = 0; mf < 2; mf++)
#pragma unroll
                for (int nf = 0; nf < 4; nf++) {
                    mma_bf16(acc[mf][nf], ah[mf], bh[nf]);
                    mma_bf16(acc[mf][nf], al[mf], bh[nf]);
                    mma_bf16(acc[mf][nf], ah[mf], bl[nf]);
                }
        }
    }

    // epilogue
#pragma unroll
    for (int mf = 0; mf < 2; mf++) {
#pragma unroll
        for (int nf = 0; nf < 4; nf++) {
            int row = bm + wm + mf*16 + g;
            int col = bn + wn + nf*8 + tg*2;
            float o0 = acc[mf][nf][0], o1 = acc[mf][nf][1];
            float o2 = acc[mf][nf][2], o3 = acc[mf][nf][3];
            if (flags & 1) {
                float b0 = bias[col], b1 = bias[col+1];
                o0 += b0; o1 += b1; o2 += b0; o3 += b1;
            }
            if (flags & 2) {
                o0 = fmaxf(o0,0.f); o1 = fmaxf(o1,0.f);
                o2 = fmaxf(o2,0.f); o3 = fmaxf(o3,0.f);
            }
            size_t i0 = (size_t)row*N + col;
            size_t i1 = (size_t)(row+8)*N + col;
            if (!(flags & 8)) {
                *(float2*)&C[i0] = make_float2(o0, o1);
                *(float2*)&C[i1] = make_float2(o2, o3);
            }
            if (flags & 4) {
                uint32_t hh, ll;
                bsplit2(o0, o1, hh, ll);
                *(uint32_t*)&Ch[i0] = hh;
                *(uint32_t*)&Cl[i0] = ll;
                bsplit2(o2, o3, hh, ll);
                *(uint32_t*)&Ch[i1] = hh;
                *(uint32_t*)&Cl[i1] = ll;
            }
        }
    }
}

// ---------------------------------------------------------------------------
// Weight group-sums (6 q/k matrices)
// ---------------------------------------------------------------------------
__global__ void __launch_bounds__(256) k_wsum6(const float* __restrict__ w0,
                                               const float* __restrict__ w1,
                                               const float* __restrict__ w2,
                                               const float* __restrict__ w3,
                                               const float* __restrict__ w4,
                                               const float* __restrict__ w5,
                                               float* __restrict__ wgT)
{
    int idx = blockIdx.x*256 + threadIdx.x;
    int m = idx >> 12;
    int r = idx & 4095;
    int g = r >> 9, c = r & 511;
    const float* w = (m == 0) ? w0 : (m == 1) ? w1 : (m == 2) ? w2 :
                     (m == 3) ? w3 : (m == 4) ? w4 : w5;
    const float* p = w + (size_t)c*512 + g*64;
    float s = 0.f;
#pragma unroll 16
    for (int j = 0; j < 64; j++) s += p[j];
    wgT[m*4096 + g*512 + c] = s;
}

// ---------------------------------------------------------------------------
// qs/ks.  same!=0 -> xq==xk: single read serves both accumulator sets.
// ---------------------------------------------------------------------------
__global__ void __launch_bounds__(256) k_qks(const float* __restrict__ xq,
                                             const float* __restrict__ xk,
                                             const float* __restrict__ wgq,
                                             const float* __restrict__ wgk,
                                             float* __restrict__ qs,
                                             float* __restrict__ ks,
                                             int same)
{
    __shared__ float sq[8][512];
    __shared__ float sk[8][512];
    int t = threadIdx.x;
    for (int i = t; i < 4096; i += 256) {
        sq[i >> 9][i & 511] = wgq[i];
        sk[i >> 9][i & 511] = wgk[i];
    }
    __syncthreads();

    int w = t >> 5, lane = t & 31;
    int r = blockIdx.x*8 + w;
    const float* xqr = xq + (size_t)r*512;
    const float* xkr = xk + (size_t)r*512;

    float aq0=0,aq1=0,aq2=0,aq3=0,aq4=0,aq5=0,aq6=0,aq7=0;
    float ak0=0,ak1=0,ak2=0,ak3=0,ak4=0,ak5=0,ak6=0,ak7=0;
#pragma unroll 4
    for (int i = 0; i < 16; i++) {
        int c = lane + 32*i;
        float xv = xqr[c];
        float kv = same ? xv : xkr[c];
        aq0 = fmaf(xv, sq[0][c], aq0);  ak0 = fmaf(kv, sk[0][c], ak0);
        aq1 = fmaf(xv, sq[1][c], aq1);  ak1 = fmaf(kv, sk[1][c], ak1);
        aq2 = fmaf(xv, sq[2][c], aq2);  ak2 = fmaf(kv, sk[2][c], ak2);
        aq3 = fmaf(xv, sq[3][c], aq3);  ak3 = fmaf(kv, sk[3][c], ak3);
        aq4 = fmaf(xv, sq[4][c], aq4);  ak4 = fmaf(kv, sk[4][c], ak4);
        aq5 = fmaf(xv, sq[5][c], aq5);  ak5 = fmaf(kv, sk[5][c], ak5);
        aq6 = fmaf(xv, sq[6][c], aq6);  ak6 = fmaf(kv, sk[6][c], ak6);
        aq7 = fmaf(xv, sq[7][c], aq7);  ak7 = fmaf(kv, sk[7][c], ak7);
    }
#pragma unroll
    for (int o = 16; o; o >>= 1) {
        aq0 += __shfl_xor_sync(~0u, aq0, o);  ak0 += __shfl_xor_sync(~0u, ak0, o);
        aq1 += __shfl_xor_sync(~0u, aq1, o);  ak1 += __shfl_xor_sync(~0u, ak1, o);
        aq2 += __shfl_xor_sync(~0u, aq2, o);  ak2 += __shfl_xor_sync(~0u, ak2, o);
        aq3 += __shfl_xor_sync(~0u, aq3, o);  ak3 += __shfl_xor_sync(~0u, ak3, o);
        aq4 += __shfl_xor_sync(~0u, aq4, o);  ak4 += __shfl_xor_sync(~0u, ak4, o);
        aq5 += __shfl_xor_sync(~0u, aq5, o);  ak5 += __shfl_xor_sync(~0u, ak5, o);
        aq6 += __shfl_xor_sync(~0u, aq6, o);  ak6 += __shfl_xor_sync(~0u, ak6, o);
        aq7 += __shfl_xor_sync(~0u, aq7, o);  ak7 += __shfl_xor_sync(~0u, ak7, o);
    }
    if (lane == 0) {
        float* q = qs + r*8;
        q[0]=aq0; q[1]=aq1; q[2]=aq2; q[3]=aq3; q[4]=aq4; q[5]=aq5; q[6]=aq6; q[7]=aq7;
    } else if (lane == 1) {
        float* k = ks + r*8;
        k[0]=ak0; k[1]=ak1; k[2]=ak2; k[3]=ak3; k[4]=ak4; k[5]=ak5; k[6]=ak6; k[7]=ak7;
    }
}

// ---------------------------------------------------------------------------
// Attention prep
// ---------------------------------------------------------------------------
__global__ void __launch_bounds__(256) k_attn_prep(const float* __restrict__ rel,
                                                   const float* __restrict__ ks,
                                                   float* __restrict__ A2,
                                                   float* __restrict__ S1)
{
    __shared__ float tile[4096];
    __shared__ float kss[64];
    __shared__ float a1p[64][4];
    __shared__ float a2p[64][4];

    int lh = blockIdx.x;
    int l  = lh >> 3, h = lh & 7;
    int t  = threadIdx.x;

    const float* rp = rel + (size_t)lh*4096;
    for (int i = t; i < 4096; i += 256) tile[i] = rp[i];
    if (t < 64) kss[t] = ks[(l << 9) + (t << 3) + h];
    __syncthreads();

    int kk = t & 63, q = t >> 6;
    float a1 = 0.f, a2 = 0.f;
    int base = 127*kk + 63;
    for (int m = q*16; m < q*16 + 16; m++) {
        int p = base + m;
        int c = p & 127;
        if (c < 64) {
            float a = tile[((p >> 7) << 6) + c];
            float km = kss[m];
            a1 = fmaf(km, a, a1);
            a2 = fmaf(km - 1e9f*(float)m, a, a2);
        }
    }
    a1p[kk][q] = a1;
    a2p[kk][q] = a2;
    __syncthreads();

    if (t < 64) {
        float A1v = a1p[t][0] + a1p[t][1] + a1p[t][2] + a1p[t][3];
        float A2v = a2p[t][0] + a2p[t][1] + a2p[t][2] + a2p[t][3];
        A2[lh*64 + t] = A2v;
        a1p[t][0] = A1v;
    }
    __syncthreads();
    if (t == 0) {
        float s = 0.f;
        for (int i = 0; i < 64; i++) s += a1p[i][0];
        S1[lh] = s;
    }
}

// ---------------------------------------------------------------------------
// FUSED attention + residual + LN, two-phase (1 block barrier total).
// Phase 1: 8 iterations, warp w computes j=it*8+w -> obufAll[it][w*64+n].
// Phase 2: warp w owns row it=w (r = l*64+h*8+w), warp-local LN, 16 cols/lane.
// ---------------------------------------------------------------------------
__global__ void __launch_bounds__(256) k_attn_ln(
    const float* __restrict__ Yv, const float* __restrict__ qs,
    const float* __restrict__ A2, const float* __restrict__ S1,
    const float* __restrict__ X, float* __restrict__ out,
    __nv_bfloat16* __restrict__ oh, __nv_bfloat16* __restrict__ ol,
    int causal, int dosplit)
{
    __shared__ float vtile[64][64];
    __shared__ float a2s[64];
    __shared__ float qss[64];
    __shared__ float ps[8][64];
    __shared__ __align__(16) float obufAll[8][512];

    int lh = blockIdx.x;
    int l = lh >> 3, h = lh & 7;
    int t = threadIdx.x, w = t >> 5, lane = t & 31;

    const float* vbase = Yv + (size_t)l*32768 + h*64;
    for (int i = t; i < 4096; i += 256) {
        int kk = i >> 6, n = i & 63;
        vtile[kk][n] = vbase[(size_t)kk*512 + n];
    }
    if (t < 64) {
        a2s[t] = A2[lh*64 + t];
        qss[t] = qs[(l << 9) + (t << 3) + h];
    }
    __syncthreads();

    float cb = SC2 * S1[lh];

    // ---- Phase 1: all 64 j's, no block syncs ----
#pragma unroll
    for (int it = 0; it < 8; it++) {
        int j = it*8 + w;
        float cj = cb * qss[j];
        float s0 = cj * a2s[lane];
        float s1 = cj * a2s[lane + 32];
        if (causal) {
            if (lane > j)      s0 += -1e9f;
            if (lane + 32 > j) s1 += -1e9f;
        }
        float mx = fmaxf(s0, s1);
#pragma unroll
        for (int o = 16; o; o >>= 1) mx = fmaxf(mx, __shfl_xor_sync(~0u, mx, o));
        float e0 = expf(s0 - mx), e1 = expf(s1 - mx);
        float sum = e0 + e1;
#pragma unroll
        for (int o = 16; o; o >>= 1) sum += __shfl_xor_sync(~0u, sum, o);
        float inv = 1.f / sum;
        ps[w][lane]      = e0 * inv;
        ps[w][lane + 32] = e1 * inv;
        __syncwarp();

        float acc0 = 0.f, acc1 = 0.f;
#pragma unroll 8
        for (int kk = 0; kk < 64; kk++) {
            float p = ps[w][kk];
            acc0 = fmaf(p, vtile[kk][lane],      acc0);
            acc1 = fmaf(p, vtile[kk][lane + 32], acc1);
        }
        // j = it*8 + w contributes row `it`, columns w*64 + n
        obufAll[it][w*64 + lane]      = acc0;
        obufAll[it][w*64 + lane + 32] = acc1;
        __syncwarp();
    }
    __syncthreads();

    // ---- Phase 2: warp w -> row it=w, warp-local LN ----
    size_t r = (size_t)l*64 + h*8 + w;
    size_t rb = r*512 + lane*16;
    float v[16];
    float sm = 0.f, sq = 0.f;
#pragma unroll
    for (int c4 = 0; c4 < 4; c4++) {
        float4 xv = *(const float4*)(X + rb + c4*4);
        float* ob = &obufAll[w][lane*16 + c4*4];
        float a0 = xv.x + ob[0];
        float a1 = xv.y + ob[1];
        float a2v = xv.z + ob[2];
        float a3 = xv.w + ob[3];
        v[c4*4]   = a0; v[c4*4+1] = a1; v[c4*4+2] = a2v; v[c4*4+3] = a3;
        sm += (a0 + a1) + (a2v + a3);
        sq += (a0*a0 + a1*a1) + (a2v*a2v + a3*a3);
    }
#pragma unroll
    for (int o = 16; o; o >>= 1) {
        sm += __shfl_xor_sync(~0u, sm, o);
        sq += __shfl_xor_sync(~0u, sq, o);
    }
    float mu  = sm * (1.f/512.f);
    float var = sq * (1.f/512.f) - mu*mu;
    float invs = 1.f / sqrtf(var + 1e-5f);
#pragma unroll
    for (int c4 = 0; c4 < 4; c4++) {
        float o0 = (v[c4*4]   - mu)*invs;
        float o1 = (v[c4*4+1] - mu)*invs;
        float o2 = (v[c4*4+2] - mu)*invs;
        float o3 = (v[c4*4+3] - mu)*invs;
        *(float4*)(out + rb + c4*4) = make_float4(o0, o1, o2, o3);
        if (dosplit) {
            uint4 H, L;
            bsplit2(o0, o1, H.x, L.x);
            bsplit2(o2, o3, H.y, L.y);
            *(uint2*)&oh[rb + c4*4] = make_uint2(H.x, H.y);
            *(uint2*)&ol[rb + c4*4] = make_uint2(L.x, L.y);
        }
    }
}

// ---------------------------------------------------------------------------
// out = LayerNorm(X + Y), 4 rows/block, float4; optional split output.
// ---------------------------------------------------------------------------
__global__ void __launch_bounds__(512) k_addln4(const float* __restrict__ X,
                                                const float* __restrict__ Y,
                                                float* __restrict__ out,
                                                __nv_bfloat16* __restrict__ oh,
                                                __nv_bfloat16* __restrict__ ol,
                                                int dosplit)
{
    __shared__ float rs[4][4], rq[4][4];
    int t = threadIdx.x;
    int sub = t >> 7;
    int tt = t & 127;
    int lane = t & 31, wir = (t >> 5) & 3;
    size_t r = (size_t)blockIdx.x*4 + sub;
    size_t base = r*512 + tt*4;

    float4 xv = *(const float4*)(X + base);
    float4 yv = *(const float4*)(Y + base);
    float v0 = xv.x + yv.x, v1 = xv.y + yv.y;
    float v2 = xv.z + yv.z, v3 = xv.w + yv.w;
    float sum = (v0 + v1) + (v2 + v3);
    float sq  = (v0*v0 + v1*v1) + (v2*v2 + v3*v3);
#pragma unroll
    for (int o = 16; o; o >>= 1) {
        sum += __shfl_xor_sync(0xffffffffu, sum, o);
        sq  += __shfl_xor_sync(0xffffffffu, sq,  o);
    }
    if (lane == 0) { rs[sub][wir] = sum; rq[sub][wir] = sq; }
    __syncthreads();
    float ts = rs[sub][0] + rs[sub][1] + rs[sub][2] + rs[sub][3];
    float tq = rq[sub][0] + rq[sub][1] + rq[sub][2] + rq[sub][3];
    float mu  = ts * (1.f/512.f);
    float var = tq * (1.f/512.f) - mu*mu;
    float inv = 1.f / sqrtf(var + 1e-5f);
    float o0 = (v0 - mu)*inv, o1 = (v1 - mu)*inv;
    float o2 = (v2 - mu)*inv, o3 = (v3 - mu)*inv;
    *(float4*)(out + base) = make_float4(o0, o1, o2, o3);
    if (dosplit) {
        uint4 H, L;
        bsplit2(o0, o1, H.x, L.x);
        bsplit2(o2, o3, H.y, L.y);
        *(uint2*)&oh[base] = make_uint2(H.x, H.y);
        *(uint2*)&ol[base] = make_uint2(L.x, L.y);
    }
}

// ---------------------------------------------------------------------------
// FUSED final stage: LN(Xa + Xb) -> projection + softmax.
// ---------------------------------------------------------------------------
__global__ void __launch_bounds__(256) k_outproj3(const float* __restrict__ Xa,
                                                  const float* __restrict__ Xb,
                                                  const float* __restrict__ W,
                                                  const float* __restrict__ b,
                                                  float* __restrict__ out)
{
    __shared__ float xs[16][512];
    __shared__ float lg[16][64];
    __shared__ float rs[2][4], rq[2][4];
    int t = threadIdx.x;
    size_t r0 = (size_t)blockIdx.x * 16;
    int lane = t & 31, w = t >> 5;
    int rowpar = w >> 2, wig = w & 3;

    for (int k = 0; k < 8; k++) {
        int idx = (t + k*256)*4;
        int rr = idx >> 9, cc = idx & 511;
        size_t base = (r0 + rr)*512 + cc;
        float4 xa = *(const float4*)(Xa + base);
        float4 xb = *(const float4*)(Xb + base);
        float v0 = xa.x + xb.x, v1 = xa.y + xb.y;
        float v2 = xa.z + xb.z, v3 = xa.w + xb.w;
        float sm = (v0 + v1) + (v2 + v3);
        float sq = (v0*v0 + v1*v1) + (v2*v2 + v3*v3);
#pragma unroll
        for (int o = 16; o; o >>= 1) {
            sm += __shfl_xor_sync(~0u, sm, o);
            sq += __shfl_xor_sync(~0u, sq, o);
        }
        if (lane == 0) { rs[rowpar][wig] = sm; rq[rowpar][wig] = sq; }
        __syncthreads();
        float ts = rs[rowpar][0] + rs[rowpar][1] + rs[rowpar][2] + rs[rowpar][3];
        float tq = rq[rowpar][0] + rq[rowpar][1] + rq[rowpar][2] + rq[rowpar][3];
        float mu  = ts * (1.f/512.f);
        float var = tq * (1.f/512.f) - mu*mu;
        float inv = 1.f / sqrtf(var + 1e-5f);
        xs[rr][cc]   = (v0 - mu)*inv;
        xs[rr][cc+1] = (v1 - mu)*inv;
        xs[rr][cc+2] = (v2 - mu)*inv;
        xs[rr][cc+3] = (v3 - mu)*inv;
        __syncthreads();
    }

    int col = t & 63, g = t >> 6;
    float bcol = b[col];
    float a0 = bcol, a1 = bcol, a2 = bcol, a3 = bcol;
#pragma unroll 8
    for (int c = 0; c < 512; c++) {
        float wv = W[c*64 + col];
        a0 = fmaf(xs[g][c],    wv, a0);
        a1 = fmaf(xs[g+4][c],  wv, a1);
        a2 = fmaf(xs[g+8][c],  wv, a2);
        a3 = fmaf(xs[g+12][c], wv, a3);
    }
    lg[g][col]    = a0;
    lg[g+4][col]  = a1;
    lg[g+8][col]  = a2;
    lg[g+12][col] = a3;
    __syncthreads();

    int w8 = t >> 5;
#pragma unroll
    for (int rr2 = 0; rr2 < 2; rr2++) {
        int rr = w8*2 + rr2;
        float s0 = lg[rr][lane], s1 = lg[rr][lane + 32];
        float mx = fmaxf(s0, s1);
#pragma unroll
        for (int o = 16; o; o >>= 1) mx = fmaxf(mx, __shfl_xor_sync(~0u, mx, o));
        float e0 = expf(s0 - mx), e1 = expf(s1 - mx);
        float sm = e0 + e1;
#pragma unroll
        for (int o = 16; o; o >>= 1) sm += __shfl_xor_sync(~0u, sm, o);
        float inv = 1.f / sm;
        out[(r0 + rr)*64 + lane]      = e0 * inv;
        out[(r0 + rr)*64 + lane + 32] = e1 * inv;
    }
}

// ---------------------------------------------------------------------------
// Host orchestration
// ---------------------------------------------------------------------------
extern "C" void kernel_launch(void* const* d_in, const int* in_sizes, int n_in,
                              void* d_out, int out_size)
{
    const float* X_en   = (const float*)d_in[0];
    const float* X_de   = (const float*)d_in[1];
    const float* W_in   = (const float*)d_in[2];
    const float* B_in   = (const float*)d_in[3];
    const float* enc_wq = (const float*)d_in[4];
    const float* enc_wk = (const float*)d_in[5];
    const float* enc_wv = (const float*)d_in[6];
    const float* enc_rel= (const float*)d_in[7];
    const float* enc_w1 = (const float*)d_in[8];
    const float* enc_b1 = (const float*)d_in[9];
    const float* enc_w2 = (const float*)d_in[10];
    const float* enc_b2 = (const float*)d_in[11];
    const float* dec_wq1= (const float*)d_in[12];
    const float* dec_wk1= (const float*)d_in[13];
    const float* dec_wv1= (const float*)d_in[14];
    const float* dec_rel1=(const float*)d_in[15];
    const float* dec_wq2= (const float*)d_in[16];
    const float* dec_wk2= (const float*)d_in[17];
    const float* dec_wv2= (const float*)d_in[18];
    const float* dec_rel2=(const float*)d_in[19];
    const float* dec_w1 = (const float*)d_in[20];
    const float* dec_b1 = (const float*)d_in[21];
    const float* dec_w2 = (const float*)d_in[22];
    const float* dec_b2 = (const float*)d_in[23];
    const float* W_out  = (const float*)d_in[24];
    const float* B_out  = (const float*)d_in[25];
    float* OUT = (float*)d_out;

    static int smem_set = 0;
    if (!smem_set) {
        cudaFuncSetAttribute(k_bgemm, cudaFuncAttributeMaxDynamicSharedMemorySize,
                             GEMM_SMEM);
        smem_set = 1;
    }

    float *xen,*xde,*V,*bufA,*bufB,*enc,*ffo,*qs,*ks,*a2,*s1,*wg;
    cudaGetSymbolAddress((void**)&xen,  g_xen);
    cudaGetSymbolAddress((void**)&xde,  g_xde);
    cudaGetSymbolAddress((void**)&V,    g_v);
    cudaGetSymbolAddress((void**)&bufA, g_bufA);
    cudaGetSymbolAddress((void**)&bufB, g_bufB);
    cudaGetSymbolAddress((void**)&enc,  g_enc);
    cudaGetSymbolAddress((void**)&ffo,  g_ffo);
    cudaGetSymbolAddress((void**)&qs,   g_qs);
    cudaGetSymbolAddress((void**)&ks,   g_ks);
    cudaGetSymbolAddress((void**)&a2,   g_a2);
    cudaGetSymbolAddress((void**)&s1,   g_s1);
    cudaGetSymbolAddress((void**)&wg,   g_wg);

    __nv_bfloat16 *sxen_h,*sxen_l,*sxde_h,*sxde_l,*xen_h,*xen_l,*xde_h,*xde_l;
    __nv_bfloat16 *enc_h,*enc_l,*bufA_h,*bufA_l,*bufB_h,*bufB_l,*ffh_h,*ffh_l;
    __nv_bfloat16 *win_h,*win_l,*wsp_h,*wsp_l;
    cudaGetSymbolAddress((void**)&sxen_h, g_sxen_h);
    cudaGetSymbolAddress((void**)&sxen_l, g_sxen_l);
    cudaGetSymbolAddress((void**)&sxde_h, g_sxde_h);
    cudaGetSymbolAddress((void**)&sxde_l, g_sxde_l);
    cudaGetSymbolAddress((void**)&xen_h,  g_xen_h);
    cudaGetSymbolAddress((void**)&xen_l,  g_xen_l);
    cudaGetSymbolAddress((void**)&xde_h,  g_xde_h);
    cudaGetSymbolAddress((void**)&xde_l,  g_xde_l);
    cudaGetSymbolAddress((void**)&enc_h,  g_enc_h);
    cudaGetSymbolAddress((void**)&enc_l,  g_enc_l);
    cudaGetSymbolAddress((void**)&bufA_h, g_bufA_h);
    cudaGetSymbolAddress((void**)&bufA_l, g_bufA_l);
    cudaGetSymbolAddress((void**)&bufB_h, g_bufB_h);
    cudaGetSymbolAddress((void**)&bufB_l, g_bufB_l);
    cudaGetSymbolAddress((void**)&ffh_h,  g_ffh_h);
    cudaGetSymbolAddress((void**)&ffh_l,  g_ffh_l);
    cudaGetSymbolAddress((void**)&win_h,  g_win_h);
    cudaGetSymbolAddress((void**)&win_l,  g_win_l);
    cudaGetSymbolAddress((void**)&wsp_h,  g_wsp_h);
    cudaGetSymbolAddress((void**)&wsp_l,  g_wsp_l);

    dim3 g512(8,128), g2048(32,128);

    // Launch order: slots 6/7 are k_qks / k_attn_prep (profiling targets)
    k_wsum6<<<96, 256>>>(enc_wq, enc_wk, dec_wq1, dec_wk1, dec_wq2, dec_wk2, wg); // 1
    k_split<<<1024, 256>>>(X_en, sxen_h, sxen_l, 4194304);           // 2
    k_split<<<8, 256>>>(W_in, win_h, win_l, 32768);                  // 3
    k_bgemm<<<g512, 256, GEMM_SMEM>>>(sxen_h, sxen_l, win_h, win_l, B_in,
                                      xen, xen_h, xen_l,
                                      NROW, 512, 64, 1|4);           // 4 embed_en
    k_split<<<64, 256>>>(enc_wv, wsp_h + WV0, wsp_l + WV0, 262144);  // 5
    k_qks<<<2048, 256>>>(xen, xen, wg + 0*4096, wg + 1*4096, qs, ks, 1); // 6
    k_attn_prep<<<LLEN*HN, 256>>>(enc_rel, ks, a2, s1);              // 7
    k_bgemm<<<g512, 256, GEMM_SMEM>>>(xen_h, xen_l, wsp_h + WV0, wsp_l + WV0,
                                      nullptr, V, nullptr, nullptr,
                                      NROW, 512, 512, 0);            // 8 V_enc
    k_split<<<1024, 256>>>(X_de, sxde_h, sxde_l, 4194304);
    k_bgemm<<<g512, 256, GEMM_SMEM>>>(sxde_h, sxde_l, win_h, win_l, B_in,
                                      xde, xde_h, xde_l,
                                      NROW, 512, 64, 1|4);           // embed_de

    // remaining weight splits
    k_split<<<64,  256>>>(dec_wv1, wsp_h + WV1, wsp_l + WV1, 262144);
    k_split<<<64,  256>>>(dec_wv2, wsp_h + WV2, wsp_l + WV2, 262144);
    k_split<<<256, 256>>>(enc_w1,  wsp_h + W1E, wsp_l + W1E, 1048576);
    k_split<<<256, 256>>>(enc_w2,  wsp_h + W2E, wsp_l + W2E, 1048576);
    k_split<<<256, 256>>>(dec_w1,  wsp_h + W1D, wsp_l + W1D, 1048576);
    k_split<<<256, 256>>>(dec_w2,  wsp_h + W2D, wsp_l + W2D, 1048576);

    // ---- encoder ----
    k_attn_ln<<<LLEN*HN, 256>>>(V, qs, a2, s1, xen, bufA, bufA_h, bufA_l, 0, 1);
    k_bgemm<<<g2048, 256, GEMM_SMEM>>>(bufA_h, bufA_l, wsp_h + W1E, wsp_l + W1E,
                                       enc_b1, nullptr, ffh_h, ffh_l,
                                       NROW, DFF, 512, 1|2|4|8);
    k_bgemm<<<g512, 256, GEMM_SMEM>>>(ffh_h, ffh_l, wsp_h + W2E, wsp_l + W2E,
                                      enc_b2, ffo, nullptr, nullptr,
                                      NROW, 512, DFF, 1);
    k_addln4<<<4096, 512>>>(bufA, ffo, enc, enc_h, enc_l, 1);

    // ---- decoder self-attn (causal) ----
    k_bgemm<<<g512, 256, GEMM_SMEM>>>(xde_h, xde_l, wsp_h + WV1, wsp_l + WV1,
                                      nullptr, V, nullptr, nullptr,
                                      NROW, 512, 512, 0);
    k_qks<<<2048, 256>>>(xde, xde, wg + 2*4096, wg + 3*4096, qs, ks, 1);
    k_attn_prep<<<LLEN*HN, 256>>>(dec_rel1, ks, a2, s1);
    k_attn_ln<<<LLEN*HN, 256>>>(V, qs, a2, s1, xde, bufA, bufA_h, bufA_l, 1, 0);

    // ---- decoder cross-attn ----
    k_bgemm<<<g512, 256, GEMM_SMEM>>>(enc_h, enc_l, wsp_h + WV2, wsp_l + WV2,
                                      nullptr, V, nullptr, nullptr,
                                      NROW, 512, 512, 0);
    k_qks<<<2048, 256>>>(bufA, enc, wg + 4*4096, wg + 5*4096, qs, ks, 0);
    k_attn_prep<<<LLEN*HN, 256>>>(dec_rel2, ks, a2, s1);
    k_attn_ln<<<LLEN*HN, 256>>>(V, qs, a2, s1, bufA, bufB, bufB_h, bufB_l, 0, 1);

    // ---- decoder FFN ----
    k_bgemm<<<g2048, 256, GEMM_SMEM>>>(bufB_h, bufB_l, wsp_h + W1D, wsp_l + W1D,
                                       dec_b1, nullptr, ffh_h, ffh_l,
                                       NROW, DFF, 512, 1|2|4|8);
    k_bgemm<<<g512, 256, GEMM_SMEM>>>(ffh_h, ffh_l, wsp_h + W2D, wsp_l + W2D,
                                      dec_b2, ffo, nullptr, nullptr,
                                      NROW, 512, DFF, 1);

    // ---- fused final LN + output projection + softmax ----
    k_outproj3<<<1024, 256>>>(bufB, ffo, W_out, B_out, OUT);

    (void)in_sizes; (void)n_in; (void)out_size;
}

// round 16
// speedup vs baseline: 1.0360x; 1.0360x over previous
#include <cuda_runtime.h>
#include <cuda_bf16.h>
#include <math.h>
#include <stdint.h>

// ---------------------------------------------------------------------------
// Problem constants
// ---------------------------------------------------------------------------
#define NROW  16384
#define DMODEL 512
#define DFF   2048
#define LLEN  256
#define HN    8
#define NSEG  (NROW*8)
#define SC2   (1.0f/64.0f)

// ---------------------------------------------------------------------------
// Scratch (fp32)
// ---------------------------------------------------------------------------
__device__ float g_xen [NROW*DMODEL];
__device__ float g_xde [NROW*DMODEL];
__device__ float g_v   [NROW*DMODEL];
__device__ float g_v2  [NROW*DMODEL];
__device__ float g_m   [NROW*DMODEL];
__device__ float g_bufA[NROW*DMODEL];
__device__ float g_bufB[NROW*DMODEL];
__device__ float g_enc [NROW*DMODEL];
__device__ float g_ffo [NROW*DMODEL];
__device__ float g_qs  [NSEG],  g_ks  [NSEG];
__device__ float g_qs2 [NSEG],  g_ks2 [NSEG];
__device__ float g_a2  [LLEN*HN*64], g_s1 [LLEN*HN];
__device__ float g_a2b [LLEN*HN*64], g_s1b[LLEN*HN];
__device__ float g_wg  [6*8*512];

// Split bf16 buffers (hi/lo)
__device__ __nv_bfloat16 g_sxen_h[4194304], g_sxen_l[4194304];
__device__ __nv_bfloat16 g_sxde_h[4194304], g_sxde_l[4194304];
__device__ __nv_bfloat16 g_xen_h [NROW*DMODEL], g_xen_l [NROW*DMODEL];
__device__ __nv_bfloat16 g_xde_h [NROW*DMODEL], g_xde_l [NROW*DMODEL];
__device__ __nv_bfloat16 g_enc_h [NROW*DMODEL], g_enc_l [NROW*DMODEL];
__device__ __nv_bfloat16 g_bufA_h[NROW*DMODEL], g_bufA_l[NROW*DMODEL];
__device__ __nv_bfloat16 g_bufB_h[NROW*DMODEL], g_bufB_l[NROW*DMODEL];
__device__ __nv_bfloat16 g_ffh_h [NROW*DFF],    g_ffh_l [NROW*DFF];
__device__ __nv_bfloat16 g_win_h [32768],       g_win_l [32768];
#define NWSPLIT 4980736
__device__ __nv_bfloat16 g_wsp_h[NWSPLIT], g_wsp_l[NWSPLIT];
#define WV0 0
#define WV1 262144
#define WV2 524288
#define W1E 786432
#define W2E 1835008
#define W1D 2883584
#define W2D 3932160

// ---------------------------------------------------------------------------
// Helpers
// ---------------------------------------------------------------------------
__device__ __forceinline__ uint32_t smem_u32(const void* p) {
    return (uint32_t)__cvta_generic_to_shared(p);
}
__device__ __forceinline__ void ldsm_x4(uint32_t* r, uint32_t addr) {
    asm volatile("ldmatrix.sync.aligned.m8n8.x4.shared.b16 {%0,%1,%2,%3}, [%4];"
        : "=r"(r[0]), "=r"(r[1]), "=r"(r[2]), "=r"(r[3]) : "r"(addr));
}
__device__ __forceinline__ void ldsm_x4t(uint32_t* r, uint32_t addr) {
    asm volatile("ldmatrix.sync.aligned.m8n8.x4.trans.shared.b16 {%0,%1,%2,%3}, [%4];"
        : "=r"(r[0]), "=r"(r[1]), "=r"(r[2]), "=r"(r[3]) : "r"(addr));
}
__device__ __forceinline__ void mma_bf16(float* c, const uint32_t* a, const uint32_t* b) {
    asm volatile(
        "mma.sync.aligned.m16n8k16.row.col.f32.bf16.bf16.f32 "
        "{%0,%1,%2,%3},{%4,%5,%6,%7},{%8,%9},{%0,%1,%2,%3};"
        : "+f"(c[0]), "+f"(c[1]), "+f"(c[2]), "+f"(c[3])
        : "r"(a[0]), "r"(a[1]), "r"(a[2]), "r"(a[3]), "r"(b[0]), "r"(b[1]));
}
__device__ __forceinline__ void cp16(uint32_t dst, const void* src) {
    asm volatile("cp.async.cg.shared.global [%0], [%1], 16;" :: "r"(dst), "l"(src));
}
__device__ __forceinline__ void cp_commit() {
    asm volatile("cp.async.commit_group;");
}
template<int N> __device__ __forceinline__ void cp_wait() {
    asm volatile("cp.async.wait_group %0;" :: "n"(N));
}
__device__ __forceinline__ void bsplit(float x, unsigned short& h, unsigned short& l) {
    __nv_bfloat16 hb = __float2bfloat16(x);
    float r = x - __bfloat162float(hb);
    h = __bfloat16_as_ushort(hb);
    l = __bfloat16_as_ushort(__float2bfloat16(r));
}
__device__ __forceinline__ void bsplit2(float a, float b, uint32_t& hh, uint32_t& ll) {
    unsigned short h0,l0,h1,l1;
    bsplit(a,h0,l0); bsplit(b,h1,l1);
    hh = (uint32_t)h0 | ((uint32_t)h1 << 16);
    ll = (uint32_t)l0 | ((uint32_t)l1 << 16);
}

// ---------------------------------------------------------------------------
// k_split: fp32 -> (hi,lo) bf16.  16 floats/thread.
// ---------------------------------------------------------------------------
__global__ void __launch_bounds__(256) k_split(const float* __restrict__ x,
                                               __nv_bfloat16* __restrict__ hi,
                                               __nv_bfloat16* __restrict__ lo,
                                               int n)
{
    int i = (blockIdx.x*256 + threadIdx.x)*16;
    if (i >= n) return;
    float4 v0 = *(const float4*)(x + i);
    float4 v1 = *(const float4*)(x + i + 4);
    float4 v2 = *(const float4*)(x + i + 8);
    float4 v3 = *(const float4*)(x + i + 12);
    uint4 H, L;
    bsplit2(v0.x, v0.y, H.x, L.x);
    bsplit2(v0.z, v0.w, H.y, L.y);
    bsplit2(v1.x, v1.y, H.z, L.z);
    bsplit2(v1.z, v1.w, H.w, L.w);
    *(uint4*)&hi[i] = H;
    *(uint4*)&lo[i] = L;
    bsplit2(v2.x, v2.y, H.x, L.x);
    bsplit2(v2.z, v2.w, H.y, L.y);
    bsplit2(v3.x, v3.y, H.z, L.z);
    bsplit2(v3.z, v3.w, H.w, L.w);
    *(uint4*)&hi[i + 8] = H;
    *(uint4*)&lo[i + 8] = L;
}

// ---------------------------------------------------------------------------
// Pipelined split-bf16 tensor GEMM (3 passes).
// Tile 128x64x32, 256 threads, 8 warps (4m x 2n), 2 CTA/SM.
// flags: b0 bias, b1 relu, b2 write split (Ch,Cl), b3 skip fp32 C.
// ---------------------------------------------------------------------------
#define STAGE_BYTES 28672
#define OFF_AL 10240
#define OFF_BH 20480
#define OFF_BL 24576
#define GEMM_SMEM (3*STAGE_BYTES)

extern __shared__ char dsm[];

__device__ __forceinline__ void ld_stage(uint32_t sb,
    const __nv_bfloat16* __restrict__ Ah, const __nv_bfloat16* __restrict__ Al,
    const __nv_bfloat16* __restrict__ Bh, const __nv_bfloat16* __restrict__ Bl,
    int K, int N, int bm, int bn, int tid, int k0)
{
    int rowA = tid >> 2, kc = tid & 3;
    size_t aoff0 = (size_t)(bm + rowA)*K + k0 + kc*8;
    size_t aoff1 = aoff0 + (size_t)64*K;
    uint32_t dA = sb + rowA*80 + kc*16;
    cp16(dA,            Ah + aoff0);
    cp16(dA + 64*80,    Ah + aoff1);
    cp16(dA + OFF_AL,         Al + aoff0);
    cp16(dA + OFF_AL + 64*80, Al + aoff1);

    int kr = tid >> 3, nc = tid & 7;
    size_t boff = (size_t)(k0 + kr)*N + bn + nc*8;
    uint32_t dB = sb + OFF_BH + kr*128 + ((nc ^ (kr & 7)) << 4);
    cp16(dB,        Bh + boff);
    cp16(dB + 4096, Bl + boff);
}

__global__ void __launch_bounds__(256, 2) k_bgemm(
    const __nv_bfloat16* __restrict__ Ah, const __nv_bfloat16* __restrict__ Al,
    const __nv_bfloat16* __restrict__ Bh, const __nv_bfloat16* __restrict__ Bl,
    const float* __restrict__ bias, float* __restrict__ C,
    __nv_bfloat16* __restrict__ Ch, __nv_bfloat16* __restrict__ Cl,
    int M, int N, int K, int flags)
{
    const int tid = threadIdx.x;
    const int bm = blockIdx.y * 128;
    const int bn = blockIdx.x * 64;
    const int w = tid >> 5, lane = tid & 31;
    const int wm = (w >> 1) * 32;
    const int wn = (w & 1) * 32;
    const int g = lane >> 2, tg = lane & 3;
    const uint32_t sbase = smem_u32(dsm);

    float acc[2][4][4];
#pragma unroll
    for (int mf = 0; mf < 2; mf++)
#pragma unroll
        for (int nf = 0; nf < 4; nf++)
#pragma unroll
            for (int i = 0; i < 4; i++) acc[mf][nf][i] = 0.f;

    const int a_off0 = (wm + (lane & 15))*40 + (lane >> 4)*8;
    const int bkl  = (lane & 7) + ((lane >> 3) & 1)*8;
    const int bncl = lane >> 4;

    const int T = K / 32;

    ld_stage(sbase,               Ah, Al, Bh, Bl, K, N, bm, bn, tid, 0);
    cp_commit();
    ld_stage(sbase + STAGE_BYTES, Ah, Al, Bh, Bl, K, N, bm, bn, tid, 32);
    cp_commit();

    for (int kt = 0; kt < T; ++kt) {
        cp_wait<1>();
        __syncthreads();

        if (kt + 2 < T) {
            int buf = (kt + 2) % 3;
            ld_stage(sbase + buf*STAGE_BYTES, Ah, Al, Bh, Bl, K, N, bm, bn,
                     tid, (kt + 2)*32);
        }
        cp_commit();

        const uint32_t bA = sbase + (kt % 3)*STAGE_BYTES;
        const uint32_t bB = bA + OFF_BH;
#pragma unroll
        for (int ks2 = 0; ks2 < 32; ks2 += 16) {
            uint32_t ah[2][4], al[2][4];
#pragma unroll
            for (int mf = 0; mf < 2; mf++) {
                int eoff = a_off0 + mf*640 + ks2;
                ldsm_x4(ah[mf], bA + 2*eoff);
                ldsm_x4(al[mf], bA + OFF_AL + 2*eoff);
            }
            uint32_t bh[4][2], bl[4][2];
#pragma unroll
            for (int nf2 = 0; nf2 < 2; nf2++) {
                int k = ks2 + bkl;
                int nc = (wn >> 3) + nf2*2 + bncl;
                int eoff = k*64 + ((nc ^ (k & 7)) << 3);
                uint32_t r[4];
                ldsm_x4t(r, bB + 2*eoff);
                bh[nf2*2][0] = r[0]; bh[nf2*2][1] = r[1];
                bh[nf2*2+1][0] = r[2]; bh[nf2*2+1][1] = r[3];
                ldsm_x4t(r, bB + 4096 + 2*eoff);
                bl[nf2*2][0] = r[0]; bl[nf2*2][1] = r[1];
                bl[nf2*2+1][0] = r[2]; bl[nf2*2+1][1] = r[3];
            }
#pragma unroll
            for (int mf = 0; mf < 2; mf++)
#pragma unroll
                for (int nf = 0; nf < 4; nf++) {
                    mma_bf16(acc[mf][nf], ah[mf], bh[nf]);
                    mma_bf16(acc[mf][nf], al[mf], bh[nf]);
                    mma_bf16(acc[mf][nf], ah[mf], bl[nf]);
                }
        }
    }

    // epilogue
#pragma unroll
    for (int mf = 0; mf < 2; mf++) {
#pragma unroll
        for (int nf = 0; nf < 4; nf++) {
            int row = bm + wm + mf*16 + g;
            int col = bn + wn + nf*8 + tg*2;
            float o0 = acc[mf][nf][0], o1 = acc[mf][nf][1];
            float o2 = acc[mf][nf][2], o3 = acc[mf][nf][3];
            if (flags & 1) {
                float b0 = bias[col], b1 = bias[col+1];
                o0 += b0; o1 += b1; o2 += b0; o3 += b1;
            }
            if (flags & 2) {
                o0 = fmaxf(o0,0.f); o1 = fmaxf(o1,0.f);
                o2 = fmaxf(o2,0.f); o3 = fmaxf(o3,0.f);
            }
            size_t i0 = (size_t)row*N + col;
            size_t i1 = (size_t)(row+8)*N + col;
            if (!(flags & 8)) {
                *(float2*)&C[i0] = make_float2(o0, o1);
                *(float2*)&C[i1] = make_float2(o2, o3);
            }
            if (flags & 4) {
                uint32_t hh, ll;
                bsplit2(o0, o1, hh, ll);
                *(uint32_t*)&Ch[i0] = hh;
                *(uint32_t*)&Cl[i0] = ll;
                bsplit2(o2, o3, hh, ll);
                *(uint32_t*)&Ch[i1] = hh;
                *(uint32_t*)&Cl[i1] = ll;
            }
        }
    }
}

// ---------------------------------------------------------------------------
// Weight group-sums (6 q/k matrices)
// ---------------------------------------------------------------------------
__global__ void __launch_bounds__(256) k_wsum6(const float* __restrict__ w0,
                                               const float* __restrict__ w1,
                                               const float* __restrict__ w2,
                                               const float* __restrict__ w3,
                                               const float* __restrict__ w4,
                                               const float* __restrict__ w5,
                                               float* __restrict__ wgT)
{
    int idx = blockIdx.x*256 + threadIdx.x;
    int m = idx >> 12;
    int r = idx & 4095;
    int g = r >> 9, c = r & 511;
    const float* w = (m == 0) ? w0 : (m == 1) ? w1 : (m == 2) ? w2 :
                     (m == 3) ? w3 : (m == 4) ? w4 : w5;
    const float* p = w + (size_t)c*512 + g*64;
    float s = 0.f;
#pragma unroll 16
    for (int j = 0; j < 64; j++) s += p[j];
    wgT[m*4096 + g*512 + c] = s;
}

// ---------------------------------------------------------------------------
// qs/ks.  same!=0 -> xq==xk: single read serves both accumulator sets.
// ---------------------------------------------------------------------------
__global__ void __launch_bounds__(256) k_qks(const float* __restrict__ xq,
                                             const float* __restrict__ xk,
                                             const float* __restrict__ wgq,
                                             const float* __restrict__ wgk,
                                             float* __restrict__ qs,
                                             float* __restrict__ ks,
                                             int same)
{
    __shared__ float sq[8][512];
    __shared__ float sk[8][512];
    int t = threadIdx.x;
    for (int i = t; i < 4096; i += 256) {
        sq[i >> 9][i & 511] = wgq[i];
        sk[i >> 9][i & 511] = wgk[i];
    }
    __syncthreads();

    int w = t >> 5, lane = t & 31;
    int r = blockIdx.x*8 + w;
    const float* xqr = xq + (size_t)r*512;
    const float* xkr = xk + (size_t)r*512;

    float aq0=0,aq1=0,aq2=0,aq3=0,aq4=0,aq5=0,aq6=0,aq7=0;
    float ak0=0,ak1=0,ak2=0,ak3=0,ak4=0,ak5=0,ak6=0,ak7=0;
#pragma unroll 4
    for (int i = 0; i < 16; i++) {
        int c = lane + 32*i;
        float xv = xqr[c];
        float kv = same ? xv : xkr[c];
        aq0 = fmaf(xv, sq[0][c], aq0);  ak0 = fmaf(kv, sk[0][c], ak0);
        aq1 = fmaf(xv, sq[1][c], aq1);  ak1 = fmaf(kv, sk[1][c], ak1);
        aq2 = fmaf(xv, sq[2][c], aq2);  ak2 = fmaf(kv, sk[2][c], ak2);
        aq3 = fmaf(xv, sq[3][c], aq3);  ak3 = fmaf(kv, sk[3][c], ak3);
        aq4 = fmaf(xv, sq[4][c], aq4);  ak4 = fmaf(kv, sk[4][c], ak4);
        aq5 = fmaf(xv, sq[5][c], aq5);  ak5 = fmaf(kv, sk[5][c], ak5);
        aq6 = fmaf(xv, sq[6][c], aq6);  ak6 = fmaf(kv, sk[6][c], ak6);
        aq7 = fmaf(xv, sq[7][c], aq7);  ak7 = fmaf(kv, sk[7][c], ak7);
    }
#pragma unroll
    for (int o = 16; o; o >>= 1) {
        aq0 += __shfl_xor_sync(~0u, aq0, o);  ak0 += __shfl_xor_sync(~0u, ak0, o);
        aq1 += __shfl_xor_sync(~0u, aq1, o);  ak1 += __shfl_xor_sync(~0u, ak1, o);
        aq2 += __shfl_xor_sync(~0u, aq2, o);  ak2 += __shfl_xor_sync(~0u, ak2, o);
        aq3 += __shfl_xor_sync(~0u, aq3, o);  ak3 += __shfl_xor_sync(~0u, ak3, o);
        aq4 += __shfl_xor_sync(~0u, aq4, o);  ak4 += __shfl_xor_sync(~0u, ak4, o);
        aq5 += __shfl_xor_sync(~0u, aq5, o);  ak5 += __shfl_xor_sync(~0u, ak5, o);
        aq6 += __shfl_xor_sync(~0u, aq6, o);  ak6 += __shfl_xor_sync(~0u, ak6, o);
        aq7 += __shfl_xor_sync(~0u, aq7, o);  ak7 += __shfl_xor_sync(~0u, ak7, o);
    }
    if (lane == 0) {
        float* q = qs + r*8;
        q[0]=aq0; q[1]=aq1; q[2]=aq2; q[3]=aq3; q[4]=aq4; q[5]=aq5; q[6]=aq6; q[7]=aq7;
    } else if (lane == 1) {
        float* k = ks + r*8;
        k[0]=ak0; k[1]=ak1; k[2]=ak2; k[3]=ak3; k[4]=ak4; k[5]=ak5; k[6]=ak6; k[7]=ak7;
    }
}

// ---------------------------------------------------------------------------
// Attention prep
// ---------------------------------------------------------------------------
__global__ void __launch_bounds__(256) k_attn_prep(const float* __restrict__ rel,
                                                   const float* __restrict__ ks,
                                                   float* __restrict__ A2,
                                                   float* __restrict__ S1)
{
    __shared__ float tile[4096];
    __shared__ float kss[64];
    __shared__ float a1p[64][4];
    __shared__ float a2p[64][4];

    int lh = blockIdx.x;
    int l  = lh >> 3, h = lh & 7;
    int t  = threadIdx.x;

    const float* rp = rel + (size_t)lh*4096;
    for (int i = t; i < 4096; i += 256) tile[i] = rp[i];
    if (t < 64) kss[t] = ks[(l << 9) + (t << 3) + h];
    __syncthreads();

    int kk = t & 63, q = t >> 6;
    float a1 = 0.f, a2 = 0.f;
    int base = 127*kk + 63;
    for (int m = q*16; m < q*16 + 16; m++) {
        int p = base + m;
        int c = p & 127;
        if (c < 64) {
            float a = tile[((p >> 7) << 6) + c];
            float km = kss[m];
            a1 = fmaf(km, a, a1);
            a2 = fmaf(km - 1e9f*(float)m, a, a2);
        }
    }
    a1p[kk][q] = a1;
    a2p[kk][q] = a2;
    __syncthreads();

    if (t < 64) {
        float A1v = a1p[t][0] + a1p[t][1] + a1p[t][2] + a1p[t][3];
        float A2v = a2p[t][0] + a2p[t][1] + a2p[t][2] + a2p[t][3];
        A2[lh*64 + t] = A2v;
        a1p[t][0] = A1v;
    }
    __syncthreads();
    if (t == 0) {
        float s = 0.f;
        for (int i = 0; i < 64; i++) s += a1p[i][0];
        S1[lh] = s;
    }
}

// ---------------------------------------------------------------------------
// FUSED attention + residual + LN, two-phase (1 block barrier total).
// ---------------------------------------------------------------------------
__global__ void __launch_bounds__(256) k_attn_ln(
    const float* __restrict__ Yv, const float* __restrict__ qs,
    const float* __restrict__ A2, const float* __restrict__ S1,
    const float* __restrict__ X, float* __restrict__ out,
    __nv_bfloat16* __restrict__ oh, __nv_bfloat16* __restrict__ ol,
    int causal, int dosplit)
{
    __shared__ float vtile[64][64];
    __shared__ float a2s[64];
    __shared__ float qss[64];
    __shared__ float ps[8][64];
    __shared__ __align__(16) float obufAll[8][512];

    int lh = blockIdx.x;
    int l = lh >> 3, h = lh & 7;
    int t = threadIdx.x, w = t >> 5, lane = t & 31;

    const float* vbase = Yv + (size_t)l*32768 + h*64;
    for (int i = t; i < 4096; i += 256) {
        int kk = i >> 6, n = i & 63;
        vtile[kk][n] = vbase[(size_t)kk*512 + n];
    }
    if (t < 64) {
        a2s[t] = A2[lh*64 + t];
        qss[t] = qs[(l << 9) + (t << 3) + h];
    }
    __syncthreads();

    float cb = SC2 * S1[lh];

#pragma unroll
    for (int it = 0; it < 8; it++) {
        int j = it*8 + w;
        float cj = cb * qss[j];
        float s0 = cj * a2s[lane];
        float s1 = cj * a2s[lane + 32];
        if (causal) {
            if (lane > j)      s0 += -1e9f;
            if (lane + 32 > j) s1 += -1e9f;
        }
        float mx = fmaxf(s0, s1);
#pragma unroll
        for (int o = 16; o; o >>= 1) mx = fmaxf(mx, __shfl_xor_sync(~0u, mx, o));
        float e0 = expf(s0 - mx), e1 = expf(s1 - mx);
        float sum = e0 + e1;
#pragma unroll
        for (int o = 16; o; o >>= 1) sum += __shfl_xor_sync(~0u, sum, o);
        float inv = 1.f / sum;
        ps[w][lane]      = e0 * inv;
        ps[w][lane + 32] = e1 * inv;
        __syncwarp();

        float acc0 = 0.f, acc1 = 0.f;
#pragma unroll 8
        for (int kk = 0; kk < 64; kk++) {
            float p = ps[w][kk];
            acc0 = fmaf(p, vtile[kk][lane],      acc0);
            acc1 = fmaf(p, vtile[kk][lane + 32], acc1);
        }
        obufAll[it][w*64 + lane]      = acc0;
        obufAll[it][w*64 + lane + 32] = acc1;
        __syncwarp();
    }
    __syncthreads();

    size_t r = (size_t)l*64 + h*8 + w;
    size_t rb = r*512 + lane*16;
    float v[16];
    float sm = 0.f, sq = 0.f;
#pragma unroll
    for (int c4 = 0; c4 < 4; c4++) {
        float4 xv = *(const float4*)(X + rb + c4*4);
        float* ob = &obufAll[w][lane*16 + c4*4];
        float a0 = xv.x + ob[0];
        float a1 = xv.y + ob[1];
        float a2v = xv.z + ob[2];
        float a3 = xv.w + ob[3];
        v[c4*4]   = a0; v[c4*4+1] = a1; v[c4*4+2] = a2v; v[c4*4+3] = a3;
        sm += (a0 + a1) + (a2v + a3);
        sq += (a0*a0 + a1*a1) + (a2v*a2v + a3*a3);
    }
#pragma unroll
    for (int o = 16; o; o >>= 1) {
        sm += __shfl_xor_sync(~0u, sm, o);
        sq += __shfl_xor_sync(~0u, sq, o);
    }
    float mu  = sm * (1.f/512.f);
    float var = sq * (1.f/512.f) - mu*mu;
    float invs = 1.f / sqrtf(var + 1e-5f);
#pragma unroll
    for (int c4 = 0; c4 < 4; c4++) {
        float o0 = (v[c4*4]   - mu)*invs;
        float o1 = (v[c4*4+1] - mu)*invs;
        float o2 = (v[c4*4+2] - mu)*invs;
        float o3 = (v[c4*4+3] - mu)*invs;
        *(float4*)(out + rb + c4*4) = make_float4(o0, o1, o2, o3);
        if (dosplit) {
            uint4 H, L;
            bsplit2(o0, o1, H.x, L.x);
            bsplit2(o2, o3, H.y, L.y);
            *(uint2*)&oh[rb + c4*4] = make_uint2(H.x, H.y);
            *(uint2*)&ol[rb + c4*4] = make_uint2(L.x, L.y);
        }
    }
}

// ---------------------------------------------------------------------------
// out = LayerNorm(X + Y), 4 rows/block, float4; optional split output.
// ---------------------------------------------------------------------------
__global__ void __launch_bounds__(512) k_addln4(const float* __restrict__ X,
                                                const float* __restrict__ Y,
                                                float* __restrict__ out,
                                                __nv_bfloat16* __restrict__ oh,
                                                __nv_bfloat16* __restrict__ ol,
                                                int dosplit)
{
    __shared__ float rs[4][4], rq[4][4];
    int t = threadIdx.x;
    int sub = t >> 7;
    int tt = t & 127;
    int lane = t & 31, wir = (t >> 5) & 3;
    size_t r = (size_t)blockIdx.x*4 + sub;
    size_t base = r*512 + tt*4;

    float4 xv = *(const float4*)(X + base);
    float4 yv = *(const float4*)(Y + base);
    float v0 = xv.x + yv.x, v1 = xv.y + yv.y;
    float v2 = xv.z + yv.z, v3 = xv.w + yv.w;
    float sum = (v0 + v1) + (v2 + v3);
    float sq  = (v0*v0 + v1*v1) + (v2*v2 + v3*v3);
#pragma unroll
    for (int o = 16; o; o >>= 1) {
        sum += __shfl_xor_sync(0xffffffffu, sum, o);
        sq  += __shfl_xor_sync(0xffffffffu, sq,  o);
    }
    if (lane == 0) { rs[sub][wir] = sum; rq[sub][wir] = sq; }
    __syncthreads();
    float ts = rs[sub][0] + rs[sub][1] + rs[sub][2] + rs[sub][3];
    float tq = rq[sub][0] + rq[sub][1] + rq[sub][2] + rq[sub][3];
    float mu  = ts * (1.f/512.f);
    float var = tq * (1.f/512.f) - mu*mu;
    float inv = 1.f / sqrtf(var + 1e-5f);
    float o0 = (v0 - mu)*inv, o1 = (v1 - mu)*inv;
    float o2 = (v2 - mu)*inv, o3 = (v3 - mu)*inv;
    *(float4*)(out + base) = make_float4(o0, o1, o2, o3);
    if (dosplit) {
        uint4 H, L;
        bsplit2(o0, o1, H.x, L.x);
        bsplit2(o2, o3, H.y, L.y);
        *(uint2*)&oh[base] = make_uint2(H.x, H.y);
        *(uint2*)&ol[base] = make_uint2(L.x, L.y);
    }
}

// ---------------------------------------------------------------------------
// FUSED final stage: LN(Xa + Xb) -> projection + softmax.
// ---------------------------------------------------------------------------
__global__ void __launch_bounds__(256) k_outproj3(const float* __restrict__ Xa,
                                                  const float* __restrict__ Xb,
                                                  const float* __restrict__ W,
                                                  const float* __restrict__ b,
                                                  float* __restrict__ out)
{
    __shared__ float xs[16][512];
    __shared__ float lg[16][64];
    __shared__ float rs[2][4], rq[2][4];
    int t = threadIdx.x;
    size_t r0 = (size_t)blockIdx.x * 16;
    int lane = t & 31, w = t >> 5;
    int rowpar = w >> 2, wig = w & 3;

    for (int k = 0; k < 8; k++) {
        int idx = (t + k*256)*4;
        int rr = idx >> 9, cc = idx & 511;
        size_t base = (r0 + rr)*512 + cc;
        float4 xa = *(const float4*)(Xa + base);
        float4 xb = *(const float4*)(Xb + base);
        float v0 = xa.x + xb.x, v1 = xa.y + xb.y;
        float v2 = xa.z + xb.z, v3 = xa.w + xb.w;
        float sm = (v0 + v1) + (v2 + v3);
        float sq = (v0*v0 + v1*v1) + (v2*v2 + v3*v3);
#pragma unroll
        for (int o = 16; o; o >>= 1) {
            sm += __shfl_xor_sync(~0u, sm, o);
            sq += __shfl_xor_sync(~0u, sq, o);
        }
        if (lane == 0) { rs[rowpar][wig] = sm; rq[rowpar][wig] = sq; }
        __syncthreads();
        float ts = rs[rowpar][0] + rs[rowpar][1] + rs[rowpar][2] + rs[rowpar][3];
        float tq = rq[rowpar][0] + rq[rowpar][1] + rq[rowpar][2] + rq[rowpar][3];
        float mu  = ts * (1.f/512.f);
        float var = tq * (1.f/512.f) - mu*mu;
        float inv = 1.f / sqrtf(var + 1e-5f);
        xs[rr][cc]   = (v0 - mu)*inv;
        xs[rr][cc+1] = (v1 - mu)*inv;
        xs[rr][cc+2] = (v2 - mu)*inv;
        xs[rr][cc+3] = (v3 - mu)*inv;
        __syncthreads();
    }

    int col = t & 63, g = t >> 6;
    float bcol = b[col];
    float a0 = bcol, a1 = bcol, a2 = bcol, a3 = bcol;
#pragma unroll 8
    for (int c = 0; c < 512; c++) {
        float wv = W[c*64 + col];
        a0 = fmaf(xs[g][c],    wv, a0);
        a1 = fmaf(xs[g+4][c],  wv, a1);
        a2 = fmaf(xs[g+8][c],  wv, a2);
        a3 = fmaf(xs[g+12][c], wv, a3);
    }
    lg[g][col]    = a0;
    lg[g+4][col]  = a1;
    lg[g+8][col]  = a2;
    lg[g+12][col] = a3;
    __syncthreads();

    int w8 = t >> 5;
#pragma unroll
    for (int rr2 = 0; rr2 < 2; rr2++) {
        int rr = w8*2 + rr2;
        float s0 = lg[rr][lane], s1 = lg[rr][lane + 32];
        float mx = fmaxf(s0, s1);
#pragma unroll
        for (int o = 16; o; o >>= 1) mx = fmaxf(mx, __shfl_xor_sync(~0u, mx, o));
        float e0 = expf(s0 - mx), e1 = expf(s1 - mx);
        float sm = e0 + e1;
#pragma unroll
        for (int o = 16; o; o >>= 1) sm += __shfl_xor_sync(~0u, sm, o);
        float inv = 1.f / sm;
        out[(r0 + rr)*64 + lane]      = e0 * inv;
        out[(r0 + rr)*64 + lane + 32] = e1 * inv;
    }
}

// ---------------------------------------------------------------------------
// Host orchestration — multi-stream fork/join (graph-capture legal)
// ---------------------------------------------------------------------------
extern "C" void kernel_launch(void* const* d_in, const int* in_sizes, int n_in,
                              void* d_out, int out_size)
{
    const float* X_en   = (const float*)d_in[0];
    const float* X_de   = (const float*)d_in[1];
    const float* W_in   = (const float*)d_in[2];
    const float* B_in   = (const float*)d_in[3];
    const float* enc_wq = (const float*)d_in[4];
    const float* enc_wk = (const float*)d_in[5];
    const float* enc_wv = (const float*)d_in[6];
    const float* enc_rel= (const float*)d_in[7];
    const float* enc_w1 = (const float*)d_in[8];
    const float* enc_b1 = (const float*)d_in[9];
    const float* enc_w2 = (const float*)d_in[10];
    const float* enc_b2 = (const float*)d_in[11];
    const float* dec_wq1= (const float*)d_in[12];
    const float* dec_wk1= (const float*)d_in[13];
    const float* dec_wv1= (const float*)d_in[14];
    const float* dec_rel1=(const float*)d_in[15];
    const float* dec_wq2= (const float*)d_in[16];
    const float* dec_wk2= (const float*)d_in[17];
    const float* dec_wv2= (const float*)d_in[18];
    const float* dec_rel2=(const float*)d_in[19];
    const float* dec_w1 = (const float*)d_in[20];
    const float* dec_b1 = (const float*)d_in[21];
    const float* dec_w2 = (const float*)d_in[22];
    const float* dec_b2 = (const float*)d_in[23];
    const float* W_out  = (const float*)d_in[24];
    const float* B_out  = (const float*)d_in[25];
    float* OUT = (float*)d_out;

    static int inited = 0;
    static cudaStream_t sDec, sW;
    static cudaEvent_t eStart, eWin, eWg, eWV, eWsp, eM;
    if (!inited) {
        cudaFuncSetAttribute(k_bgemm, cudaFuncAttributeMaxDynamicSharedMemorySize,
                             GEMM_SMEM);
        cudaStreamCreateWithFlags(&sDec, cudaStreamNonBlocking);
        cudaStreamCreateWithFlags(&sW,   cudaStreamNonBlocking);
        cudaEventCreateWithFlags(&eStart, cudaEventDisableTiming);
        cudaEventCreateWithFlags(&eWin,   cudaEventDisableTiming);
        cudaEventCreateWithFlags(&eWg,    cudaEventDisableTiming);
        cudaEventCreateWithFlags(&eWV,    cudaEventDisableTiming);
        cudaEventCreateWithFlags(&eWsp,   cudaEventDisableTiming);
        cudaEventCreateWithFlags(&eM,     cudaEventDisableTiming);
        inited = 1;
    }

    float *xen,*xde,*V,*V2,*M,*bufA,*bufB,*enc,*ffo;
    float *qs,*ks,*qs2,*ks2,*a2,*s1,*a2b,*s1b,*wg;
    cudaGetSymbolAddress((void**)&xen,  g_xen);
    cudaGetSymbolAddress((void**)&xde,  g_xde);
    cudaGetSymbolAddress((void**)&V,    g_v);
    cudaGetSymbolAddress((void**)&V2,   g_v2);
    cudaGetSymbolAddress((void**)&M,    g_m);
    cudaGetSymbolAddress((void**)&bufA, g_bufA);
    cudaGetSymbolAddress((void**)&bufB, g_bufB);
    cudaGetSymbolAddress((void**)&enc,  g_enc);
    cudaGetSymbolAddress((void**)&ffo,  g_ffo);
    cudaGetSymbolAddress((void**)&qs,   g_qs);
    cudaGetSymbolAddress((void**)&ks,   g_ks);
    cudaGetSymbolAddress((void**)&qs2,  g_qs2);
    cudaGetSymbolAddress((void**)&ks2,  g_ks2);
    cudaGetSymbolAddress((void**)&a2,   g_a2);
    cudaGetSymbolAddress((void**)&s1,   g_s1);
    cudaGetSymbolAddress((void**)&a2b,  g_a2b);
    cudaGetSymbolAddress((void**)&s1b,  g_s1b);
    cudaGetSymbolAddress((void**)&wg,   g_wg);

    __nv_bfloat16 *sxen_h,*sxen_l,*sxde_h,*sxde_l,*xen_h,*xen_l,*xde_h,*xde_l;
    __nv_bfloat16 *enc_h,*enc_l,*bufA_h,*bufA_l,*bufB_h,*bufB_l,*ffh_h,*ffh_l;
    __nv_bfloat16 *win_h,*win_l,*wsp_h,*wsp_l;
    cudaGetSymbolAddress((void**)&sxen_h, g_sxen_h);
    cudaGetSymbolAddress((void**)&sxen_l, g_sxen_l);
    cudaGetSymbolAddress((void**)&sxde_h, g_sxde_h);
    cudaGetSymbolAddress((void**)&sxde_l, g_sxde_l);
    cudaGetSymbolAddress((void**)&xen_h,  g_xen_h);
    cudaGetSymbolAddress((void**)&xen_l,  g_xen_l);
    cudaGetSymbolAddress((void**)&xde_h,  g_xde_h);
    cudaGetSymbolAddress((void**)&xde_l,  g_xde_l);
    cudaGetSymbolAddress((void**)&enc_h,  g_enc_h);
    cudaGetSymbolAddress((void**)&enc_l,  g_enc_l);
    cudaGetSymbolAddress((void**)&bufA_h, g_bufA_h);
    cudaGetSymbolAddress((void**)&bufA_l, g_bufA_l);
    cudaGetSymbolAddress((void**)&bufB_h, g_bufB_h);
    cudaGetSymbolAddress((void**)&bufB_l, g_bufB_l);
    cudaGetSymbolAddress((void**)&ffh_h,  g_ffh_h);
    cudaGetSymbolAddress((void**)&ffh_l,  g_ffh_l);
    cudaGetSymbolAddress((void**)&win_h,  g_win_h);
    cudaGetSymbolAddress((void**)&win_l,  g_win_l);
    cudaGetSymbolAddress((void**)&wsp_h,  g_wsp_h);
    cudaGetSymbolAddress((void**)&wsp_l,  g_wsp_l);

    dim3 g512(8,128), g2048(32,128);

    // ---- fork ----
    cudaEventRecord(eStart, 0);
    cudaStreamWaitEvent(sW,   eStart, 0);
    cudaStreamWaitEvent(sDec, eStart, 0);

    // ---- sW: weight preprocessing ----
    k_wsum6<<<96, 256, 0, sW>>>(enc_wq, enc_wk, dec_wq1, dec_wk1,
                                dec_wq2, dec_wk2, wg);
    cudaEventRecord(eWg, sW);
    k_split<<<64, 256, 0, sW>>>(enc_wv,  wsp_h + WV0, wsp_l + WV0, 262144);
    k_split<<<64, 256, 0, sW>>>(dec_wv1, wsp_h + WV1, wsp_l + WV1, 262144);
    k_split<<<64, 256, 0, sW>>>(dec_wv2, wsp_h + WV2, wsp_l + WV2, 262144);
    cudaEventRecord(eWV, sW);
    k_split<<<256, 256, 0, sW>>>(enc_w1, wsp_h + W1E, wsp_l + W1E, 1048576);
    k_split<<<256, 256, 0, sW>>>(enc_w2, wsp_h + W2E, wsp_l + W2E, 1048576);
    k_split<<<256, 256, 0, sW>>>(dec_w1, wsp_h + W1D, wsp_l + W1D, 1048576);
    k_split<<<256, 256, 0, sW>>>(dec_w2, wsp_h + W2D, wsp_l + W2D, 1048576);
    cudaEventRecord(eWsp, sW);

    // ---- stream 0: encoder chain ----
    k_split<<<1024, 256>>>(X_en, sxen_h, sxen_l, 4194304);
    k_split<<<8, 256>>>(W_in, win_h, win_l, 32768);
    cudaEventRecord(eWin, 0);
    k_bgemm<<<g512, 256, GEMM_SMEM>>>(sxen_h, sxen_l, win_h, win_l, B_in,
                                      xen, xen_h, xen_l, NROW, 512, 64, 1|4);
    cudaStreamWaitEvent(0, eWg, 0);
    k_qks<<<2048, 256>>>(xen, xen, wg + 0*4096, wg + 1*4096, qs, ks, 1);
    k_attn_prep<<<LLEN*HN, 256>>>(enc_rel, ks, a2, s1);
    cudaStreamWaitEvent(0, eWV, 0);
    k_bgemm<<<g512, 256, GEMM_SMEM>>>(xen_h, xen_l, wsp_h + WV0, wsp_l + WV0,
                                      nullptr, V, nullptr, nullptr,
                                      NROW, 512, 512, 0);
    k_attn_ln<<<LLEN*HN, 256>>>(V, qs, a2, s1, xen, bufA, bufA_h, bufA_l, 0, 1);
    cudaStreamWaitEvent(0, eWsp, 0);
    k_bgemm<<<g2048, 256, GEMM_SMEM>>>(bufA_h, bufA_l, wsp_h + W1E, wsp_l + W1E,
                                       enc_b1, nullptr, ffh_h, ffh_l,
                                       NROW, DFF, 512, 1|2|4|8);
    k_bgemm<<<g512, 256, GEMM_SMEM>>>(ffh_h, ffh_l, wsp_h + W2E, wsp_l + W2E,
                                      enc_b2, ffo, nullptr, nullptr,
                                      NROW, 512, DFF, 1);
    k_addln4<<<4096, 512>>>(bufA, ffo, enc, enc_h, enc_l, 1);

    // ---- sDec: decoder self-attention chain (independent of encoder) ----
    k_split<<<1024, 256, 0, sDec>>>(X_de, sxde_h, sxde_l, 4194304);
    cudaStreamWaitEvent(sDec, eWin, 0);
    k_bgemm<<<g512, 256, GEMM_SMEM, sDec>>>(sxde_h, sxde_l, win_h, win_l, B_in,
                                            xde, xde_h, xde_l, NROW, 512, 64, 1|4);
    cudaStreamWaitEvent(sDec, eWg, 0);
    k_qks<<<2048, 256, 0, sDec>>>(xde, xde, wg + 2*4096, wg + 3*4096,
                                  qs2, ks2, 1);
    k_attn_prep<<<LLEN*HN, 256, 0, sDec>>>(dec_rel1, ks2, a2b, s1b);
    cudaStreamWaitEvent(sDec, eWV, 0);
    k_bgemm<<<g512, 256, GEMM_SMEM, sDec>>>(xde_h, xde_l, wsp_h + WV1,
                                            wsp_l + WV1, nullptr, V2,
                                            nullptr, nullptr, NROW, 512, 512, 0);
    k_attn_ln<<<LLEN*HN, 256, 0, sDec>>>(V2, qs2, a2b, s1b, xde, M,
                                         bufB_h, bufB_l, 1, 0);   // m (fp32 only)
    cudaEventRecord(eM, sDec);

    // ---- stream 0: cross-attention + decoder FFN + output ----
    k_bgemm<<<g512, 256, GEMM_SMEM>>>(enc_h, enc_l, wsp_h + WV2, wsp_l + WV2,
                                      nullptr, V, nullptr, nullptr,
                                      NROW, 512, 512, 0);
    cudaStreamWaitEvent(0, eM, 0);
    k_qks<<<2048, 256>>>(M, enc, wg + 4*4096, wg + 5*4096, qs, ks, 0);
    k_attn_prep<<<LLEN*HN, 256>>>(dec_rel2, ks, a2, s1);
    k_attn_ln<<<LLEN*HN, 256>>>(V, qs, a2, s1, M, bufB, bufB_h, bufB_l, 0, 1);

    k_bgemm<<<g2048, 256, GEMM_SMEM>>>(bufB_h, bufB_l, wsp_h + W1D, wsp_l + W1D,
                                       dec_b1, nullptr, ffh_h, ffh_l,
                                       NROW, DFF, 512, 1|2|4|8);
    k_bgemm<<<g512, 256, GEMM_SMEM>>>(ffh_h, ffh_l, wsp_h + W2D, wsp_l + W2D,
                                      dec_b2, ffo, nullptr, nullptr,
                                      NROW, 512, DFF, 1);

    k_outproj3<<<1024, 256>>>(bufB, ffo, W_out, B_out, OUT);

    (void)in_sizes; (void)n_in; (void)out_size;
}